// round 11
// baseline (speedup 1.0000x reference)
#include <cuda_runtime.h>

// Problem constants (fixed by the reference)
#define Bn 32
#define Nn 1024
#define Fn 128
#define Dn 128
#define SL 16                       // slice blocks per batch
#define RPB 64                      // rows per slice block
#define SCALE 0.08838834764831843f  // 128^-0.5

// Scratch (static __device__ — no allocation allowed)
__device__ float g_XsumP[Bn][SL][Fn];
__device__ float g_u[Bn][Fn];
__device__ float g_c[Bn];
__device__ float g_agg[Bn][Nn];
__device__ float g_M[Bn][SL];
__device__ float g_S[Bn][SL];
__device__ float g_acc[Bn][SL][Fn];

// ---------------------------------------------------------------------------
// K1: column-sum partials of X. grid (B, SL) x 256. Triggers at entry.
__global__ __launch_bounds__(256, 4)
void k1(const float* __restrict__ X) {
    cudaTriggerProgrammaticLaunchCompletion();
    int b = blockIdx.x, s = blockIdx.y, t = threadIdx.x;
    int w = t >> 5, lane = t & 31;
    __shared__ float4 shP[8][32];
    const float4* Xr = (const float4*)(X + ((size_t)b * Nn + s * RPB + w * 8) * Fn);
    float4 cs = Xr[lane];
    #pragma unroll
    for (int r = 1; r < 8; r++) {
        float4 xx = Xr[(size_t)r * 32 + lane];
        cs.x += xx.x; cs.y += xx.y; cs.z += xx.z; cs.w += xx.w;
    }
    shP[w][lane] = cs;
    __syncthreads();
    if (t < 32) {
        float4 sum = shP[0][t];
        #pragma unroll
        for (int g = 1; g < 8; g++) {
            float4 p = shP[g][t];
            sum.x += p.x; sum.y += p.y; sum.z += p.z; sum.w += p.w;
        }
        ((float4*)g_XsumP[b][s])[t] = sum;
    }
}

// ---------------------------------------------------------------------------
// K2: ksum -> u, c. grid B x 256. Triggers at ENTRY (so k3 launches during
// k1 and prefetches X). Prefetches Wk+Wq into dynamic smem before its sync.
__global__ __launch_bounds__(256)
void k2(const float* __restrict__ Wq, const float* __restrict__ bq,
        const float* __restrict__ Wk, const float* __restrict__ bk) {
    cudaTriggerProgrammaticLaunchCompletion();
    extern __shared__ float dyn[];
    float* sWk = dyn;                 // [128*128]   row f, col d
    float* sWq = dyn + Fn * Dn;       // [128*129]   padded rows (no conflicts)
    int b = blockIdx.x, t = threadIdx.x;
    int w = t >> 5, lane = t & 31;
    __shared__ float Xs[Fn], Ks[Fn], part[2][Fn], red8[8];

    // ---- prefetch (independent of k1) ----
    {
        const float4* Wk4 = (const float4*)Wk;
        float4* sWk4 = (float4*)sWk;
        #pragma unroll
        for (int i = 0; i < 16; i++) sWk4[t + i * 256] = Wk4[t + i * 256];
        const float4* Wq4 = (const float4*)Wq;
        #pragma unroll
        for (int i = 0; i < 16; i++) {
            float4 v = Wq4[t + i * 256];
            int idx = (t + i * 256) * 4;
            int row = idx >> 7, col = idx & 127;
            float* p = sWq + row * 129 + col;
            p[0] = v.x; p[1] = v.y; p[2] = v.z; p[3] = v.w;
        }
    }
    cudaGridDependencySynchronize();
    __syncthreads();                                // smem prefetch visible

    if (t < 128) {
        float s0 = 0.f, s1 = 0.f, s2 = 0.f, s3 = 0.f;
        #pragma unroll
        for (int j = 0; j < SL; j += 4) {
            s0 += g_XsumP[b][j][t];
            s1 += g_XsumP[b][j + 1][t];
            s2 += g_XsumP[b][j + 2][t];
            s3 += g_XsumP[b][j + 3][t];
        }
        Xs[t] = (s0 + s1) + (s2 + s3);
    }
    __syncthreads();
    int d = t & 127, h = t >> 7;                   // half of the K range
    {
        const float* wk = sWk + (h * 64) * Dn + d;
        float a0 = 0.f, a1 = 0.f, a2 = 0.f, a3 = 0.f;
        #pragma unroll
        for (int f = 0; f < 64; f += 4) {
            a0 += Xs[h * 64 + f]     * wk[(f)     * Dn];
            a1 += Xs[h * 64 + f + 1] * wk[(f + 1) * Dn];
            a2 += Xs[h * 64 + f + 2] * wk[(f + 2) * Dn];
            a3 += Xs[h * 64 + f + 3] * wk[(f + 3) * Dn];
        }
        part[h][d] = (a0 + a1) + (a2 + a3);
    }
    __syncthreads();
    if (t < 128) Ks[t] = part[0][t] + part[1][t] + (float)Nn * bk[t];
    __syncthreads();
    {
        const float* wq = sWq + d * 129 + h * 64;
        float a0 = 0.f, a1 = 0.f, a2 = 0.f, a3 = 0.f;
        #pragma unroll
        for (int f = 0; f < 64; f += 4) {
            a0 += wq[f]     * Ks[h * 64 + f];
            a1 += wq[f + 1] * Ks[h * 64 + f + 1];
            a2 += wq[f + 2] * Ks[h * 64 + f + 2];
            a3 += wq[f + 3] * Ks[h * 64 + f + 3];
        }
        part[h][d] = (a0 + a1) + (a2 + a3);
    }
    __syncthreads();
    if (t < 128) g_u[b][t] = part[0][t] + part[1][t];
    // c = bq . Ks via warp shuffles (2 barriers instead of 7)
    float rv = (t < 128) ? bq[t] * Ks[t] : 0.f;
    #pragma unroll
    for (int off = 16; off > 0; off >>= 1)
        rv += __shfl_xor_sync(0xffffffffu, rv, off);
    if (lane == 0) red8[w] = rv;
    __syncthreads();
    if (t == 0)
        g_c[b] = ((red8[0] + red8[1]) + (red8[2] + red8[3]));
}

// ---------------------------------------------------------------------------
// K3: fused agg + softmax partials. grid (B, SL) x 256, 8 rows/warp.
// Triggers at ENTRY (k4 launches early); X + mask loads issued before the
// dependency sync so the 16 MB fetch overlaps k1+k2 (L2 hits behind k1).
__global__ __launch_bounds__(256, 4)
void k3(const float* __restrict__ X, const float* __restrict__ mask) {
    cudaTriggerProgrammaticLaunchCompletion();
    int b = blockIdx.x, s = blockIdx.y, t = threadIdx.x;
    int w = t >> 5, lane = t & 31;
    __shared__ float shU[Fn];
    __shared__ float shMw[8], shSw[8];
    __shared__ float4 shP[8][32];

    int row0 = s * RPB + w * 8;
    const float4* Xr = (const float4*)(X + ((size_t)b * Nn + row0) * Fn);
    float4 x[8];
    #pragma unroll
    for (int r = 0; r < 8; r++) x[r] = Xr[(size_t)r * 32 + lane];   // in flight
    const float* mrow = mask + b * Nn + row0;
    float mk[8];
    #pragma unroll
    for (int r = 0; r < 8; r++) mk[r] = __ldg(mrow + r);            // in flight

    cudaGridDependencySynchronize();                                 // wait for k2

    if (t < 128) shU[t] = g_u[b][t];
    __syncthreads();
    float c = g_c[b];
    float4 uv = ((float4*)shU)[lane];

    float d[8];
    #pragma unroll
    for (int r = 0; r < 8; r++)
        d[r] = x[r].x * uv.x + x[r].y * uv.y + x[r].z * uv.z + x[r].w * uv.w;
    #pragma unroll
    for (int off = 16; off > 0; off >>= 1) {
        #pragma unroll
        for (int r = 0; r < 8; r++)
            d[r] += __shfl_xor_sync(0xffffffffu, d[r], off);
    }
    float a[8];
    #pragma unroll
    for (int r = 0; r < 8; r++)
        a[r] = (mk[r] != 0.f) ? SCALE * (d[r] + c) : -1e9f;

    // store agg: lane r holds a[r]
    {
        float myA = a[0];
        #pragma unroll
        for (int r = 1; r < 8; r++) if (lane == r) myA = a[r];
        if (lane < 8) g_agg[b][row0 + lane] = myA;
    }

    float M8 = a[0];
    #pragma unroll
    for (int r = 1; r < 8; r++) M8 = fmaxf(M8, a[r]);
    float ev[8], Ssum = 0.f;
    #pragma unroll
    for (int r = 0; r < 8; r++) { ev[r] = __expf(a[r] - M8); Ssum += ev[r]; }
    float4 acc = make_float4(0.f, 0.f, 0.f, 0.f);
    #pragma unroll
    for (int r = 0; r < 8; r++) {
        acc.x += ev[r] * x[r].x; acc.y += ev[r] * x[r].y;
        acc.z += ev[r] * x[r].z; acc.w += ev[r] * x[r].w;
    }

    if (lane == 0) { shMw[w] = M8; shSw[w] = Ssum; }
    shP[w][lane] = acc;
    __syncthreads();
    if (t < 32) {
        float bM = shMw[0];
        #pragma unroll
        for (int j = 1; j < 8; j++) bM = fmaxf(bM, shMw[j]);
        float Sb = 0.f;
        float4 ya = make_float4(0.f, 0.f, 0.f, 0.f);
        #pragma unroll
        for (int j = 0; j < 8; j++) {
            float f = __expf(shMw[j] - bM);
            Sb += f * shSw[j];
            float4 p = shP[j][t];
            ya.x += f * p.x; ya.y += f * p.y; ya.z += f * p.z; ya.w += f * p.w;
        }
        ((float4*)g_acc[b][s])[t] = ya;
        if (t == 0) { g_M[b][s] = bM; g_S[b][s] = Sb; }
    }
}

// ---------------------------------------------------------------------------
// K4: finalize. grid (B, 4) x 256. i==0 blocks prefetch Wv into dynamic smem
// before the dependency sync (overlaps k1/k2/k3 bodies).
__global__ __launch_bounds__(256)
void k4(const float* __restrict__ Wv, const float* __restrict__ bv,
        float* __restrict__ attn, float* __restrict__ ctx) {
    extern __shared__ float sWv[];                // [128*128], row f col d
    int b = blockIdx.x, i = blockIdx.y, t = threadIdx.x;

    if (i == 0) {                                  // prefetch Wv (indep of k3)
        const float4* Wv4 = (const float4*)Wv;
        float4* sWv4 = (float4*)sWv;
        #pragma unroll
        for (int j = 0; j < 16; j++) sWv4[t + j * 256] = Wv4[t + j * 256];
    }
    cudaGridDependencySynchronize();               // wait for k3

    int n = i * 256 + t;
    float aggv = g_agg[b][n];                      // issue immediately

    __shared__ float shW[SL];                      // exp(M[j]-bM)
    __shared__ float shB[2];                       // bM, invZ
    if (t < 32) {
        float m = (t < SL) ? g_M[b][t] : -3.0e38f;
        float sv = (t < SL) ? g_S[b][t] : 0.f;
        float bM = m;
        #pragma unroll
        for (int off = 16; off > 0; off >>= 1)
            bM = fmaxf(bM, __shfl_xor_sync(0xffffffffu, bM, off));
        float e = __expf(m - bM);
        float z = e * sv;
        #pragma unroll
        for (int off = 16; off > 0; off >>= 1)
            z += __shfl_xor_sync(0xffffffffu, z, off);
        if (t < SL) shW[t] = e;
        if (t == 0) { shB[0] = bM; shB[1] = 1.0f / z; }
    }
    __syncthreads();
    float bM = shB[0], invZ = shB[1];

    attn[b * Nn + n] = __expf(aggv - bM) * invZ;

    if (i == 0) {
        __shared__ float shY[Fn], part[2][Fn];
        if (t < 128) {
            float y0 = 0.f, y1 = 0.f, y2 = 0.f, y3 = 0.f;
            #pragma unroll
            for (int j = 0; j < SL; j += 4) {
                y0 += shW[j]     * g_acc[b][j][t];
                y1 += shW[j + 1] * g_acc[b][j + 1][t];
                y2 += shW[j + 2] * g_acc[b][j + 2][t];
                y3 += shW[j + 3] * g_acc[b][j + 3][t];
            }
            shY[t] = ((y0 + y1) + (y2 + y3)) * invZ;
        }
        __syncthreads();
        {
            int d = t & 127, h = t >> 7;
            const float* wv = sWv + (h * 64) * Dn + d;
            float a0 = 0.f, a1 = 0.f, a2 = 0.f, a3 = 0.f;
            #pragma unroll
            for (int f = 0; f < 64; f += 4) {
                a0 += shY[h * 64 + f]     * wv[(f)     * Dn];
                a1 += shY[h * 64 + f + 1] * wv[(f + 1) * Dn];
                a2 += shY[h * 64 + f + 2] * wv[(f + 2) * Dn];
                a3 += shY[h * 64 + f + 3] * wv[(f + 3) * Dn];
            }
            part[h][d] = (a0 + a1) + (a2 + a3);
        }
        __syncthreads();
        if (t < 128)
            ctx[b * Dn + t] = bv[t] + part[0][t] + part[1][t];
    }
}

// ---------------------------------------------------------------------------
extern "C" void kernel_launch(void* const* d_in, const int* in_sizes, int n_in,
                              void* d_out, int out_size) {
    const float* X    = (const float*)d_in[0];
    const float* mask = (const float*)d_in[1];
    const float* Wq   = (const float*)d_in[2];
    const float* bq   = (const float*)d_in[3];
    const float* Wk   = (const float*)d_in[4];
    const float* bk   = (const float*)d_in[5];
    const float* Wv   = (const float*)d_in[6];
    const float* bv   = (const float*)d_in[7];
    float* out  = (float*)d_out;
    float* attn = out;              // [B,N,1]
    float* ctx  = out + Bn * Nn;    // [B,D]

    const int k2smem = (Fn * Dn + Fn * 129) * (int)sizeof(float);   // 131584
    const int k4smem = Fn * Dn * (int)sizeof(float);                // 65536
    static bool attrSet = false;
    if (!attrSet) {
        cudaFuncSetAttribute(k2, cudaFuncAttributeMaxDynamicSharedMemorySize, k2smem);
        cudaFuncSetAttribute(k4, cudaFuncAttributeMaxDynamicSharedMemorySize, k4smem);
        attrSet = true;
    }

    cudaLaunchAttribute pdlAttr;
    pdlAttr.id = cudaLaunchAttributeProgrammaticStreamSerialization;
    pdlAttr.val.programmaticStreamSerializationAllowed = 1;

    {   // k1 (triggers at entry)
        cudaLaunchConfig_t cfg = {};
        cfg.gridDim = dim3(Bn, SL); cfg.blockDim = dim3(256);
        cfg.stream = 0;
        cudaLaunchKernelEx(&cfg, k1, X);
    }
    {   // k2: PDL on k1; triggers at entry -> k3 launches during k1
        cudaLaunchConfig_t cfg = {};
        cfg.gridDim = dim3(Bn); cfg.blockDim = dim3(256);
        cfg.dynamicSmemBytes = k2smem;
        cfg.stream = 0; cfg.attrs = &pdlAttr; cfg.numAttrs = 1;
        cudaLaunchKernelEx(&cfg, k2, Wq, bq, Wk, bk);
    }
    {   // k3: PDL on k2; triggers at entry -> k4 launches during k1/k2
        cudaLaunchConfig_t cfg = {};
        cfg.gridDim = dim3(Bn, SL); cfg.blockDim = dim3(256);
        cfg.stream = 0; cfg.attrs = &pdlAttr; cfg.numAttrs = 1;
        cudaLaunchKernelEx(&cfg, k3, X, mask);
    }
    {   // k4: PDL on k3
        cudaLaunchConfig_t cfg = {};
        cfg.gridDim = dim3(Bn, 4); cfg.blockDim = dim3(256);
        cfg.dynamicSmemBytes = k4smem;
        cfg.stream = 0; cfg.attrs = &pdlAttr; cfg.numAttrs = 1;
        cudaLaunchKernelEx(&cfg, k4, Wv, bv, attn, ctx);
    }
}